// round 3
// baseline (speedup 1.0000x reference)
#include <cuda_runtime.h>

// Problem constants (fixed by the dataset)
#define BB     16384   // batch
#define TT     60
#define II     32      // input / output feature dim
#define HH     128     // hidden dim
#define STEPS  30
#define SEQOFF 30      // x[:, 30, :] is the only x slice used

#define MT   32        // batch elements per CTA
#define NTH  256       // threads per CTA

// ---------------------------------------------------------------------------
// Packed (transposed) weights in device-global scratch. Repacked every launch
// (deterministic, graph-capturable, no allocations).
//   g_Wx[k][g]  = W_ih[g][k]   k in [0,32),  g in [0,384)   (gate-major cols)
//   g_Wh[k][g]  = W_hh[g][k]   k in [0,128), g in [0,384)
//   g_Wot[k][i] = W_out[i][k]  k in [0,128), i in [0,32)
//   biases: r/z combined (b_ih + b_hh); n kept split (i_n vs h_n).
// ---------------------------------------------------------------------------
__device__ __align__(16) float g_Wx[32 * 384];
__device__ __align__(16) float g_Wh[128 * 384];
__device__ __align__(16) float g_Wot[128 * 32];
__device__ float g_br[128], g_bz[128], g_bin[128], g_bhn[128];

__global__ void pack_kernel(const float* __restrict__ W_ih,
                            const float* __restrict__ W_hh,
                            const float* __restrict__ W_out,
                            const float* __restrict__ b_ih,
                            const float* __restrict__ b_hh)
{
    int idx = blockIdx.x * blockDim.x + threadIdx.x;
    if (idx < 12288) {                       // Wx: 32*384
        int k = idx / 384, g = idx - k * 384;
        g_Wx[idx] = W_ih[g * 32 + k];
    }
    int i2 = idx - 12288;                    // Wh: 128*384
    if (i2 >= 0 && i2 < 49152) {
        int k = i2 / 384, g = i2 - k * 384;
        g_Wh[i2] = W_hh[g * 128 + k];
    }
    int i3 = idx - 61440;                    // Wot: 128*32
    if (i3 >= 0 && i3 < 4096) {
        int k = i3 >> 5, i = i3 & 31;
        g_Wot[i3] = W_out[i * 128 + k];
    }
    int i4 = idx - 65536;                    // biases
    if (i4 >= 0 && i4 < 128) {
        g_br[i4]  = b_ih[i4]        + b_hh[i4];
        g_bz[i4]  = b_ih[128 + i4]  + b_hh[128 + i4];
        g_bin[i4] = b_ih[256 + i4];
        g_bhn[i4] = b_hh[256 + i4];
    }
}

__device__ __forceinline__ float sigmoid_f(float v) {
    return __fdividef(1.0f, 1.0f + __expf(-v));
}
__device__ __forceinline__ float tanh_f(float v) {
    // 1 - 2/(e^{2v}+1): exact saturation at +/-1, ~2^-21 rel err otherwise
    return 1.0f - __fdividef(2.0f, __expf(2.0f * v) + 1.0f);
}

// ---------------------------------------------------------------------------
// Main recurrent kernel. One CTA = 32 batch elements for all 30 steps.
// Activation state stored transposed in smem: A[buf][k][m], k in [0,160)
// (rows 0..31 = x_t, rows 32..159 = h_t), row stride 36 floats (16B aligned).
// Thread tile: 4 batch (m) x 4 hidden (j) with fused r/z accumulators.
// ---------------------------------------------------------------------------
__global__ __launch_bounds__(NTH, 2)
void gru_kernel(const float* __restrict__ x,
                const float* __restrict__ h0,
                const float* __restrict__ b_out,
                float* __restrict__ out)
{
    __shared__ float A[2][160][36];

    const int tid = threadIdx.x;
    const int b0  = blockIdx.x * MT;
    const int tm4 = (tid >> 5) << 2;   // batch offset within tile: 0,4,...,28
    const int tj  = tid & 31;          // lane: j-group / output feature
    const int j4  = tj << 2;           // hidden offset: 0,4,...,124

    // ---- prologue: x0 = x[:,30,:]  and  h0 into A[0] (transposed) ----
    for (int idx = tid; idx < MT * II; idx += NTH) {
        int m = idx >> 5, i = idx & 31;
        A[0][i][m] = x[(size_t)(b0 + m) * (TT * II) + SEQOFF * II + i];
    }
    for (int idx = tid; idx < MT * HH; idx += NTH) {
        int m = idx >> 7, k = idx & 127;
        A[0][32 + k][m] = h0[(size_t)(b0 + m) * HH + k];
    }

    float br_[4], bz_[4], bin_[4], bhn_[4];
#pragma unroll
    for (int ji = 0; ji < 4; ji++) {
        br_[ji]  = g_br[j4 + ji];
        bz_[ji]  = g_bz[j4 + ji];
        bin_[ji] = g_bin[j4 + ji];
        bhn_[ji] = g_bhn[j4 + ji];
    }
    const float bo = b_out[tj];
    __syncthreads();

    for (int t = 0; t < STEPS; t++) {
        const int cur = t & 1, nxt = cur ^ 1;

        float ar[4][4], az[4][4], ain[4][4], ahn[4][4];
#pragma unroll
        for (int mi = 0; mi < 4; mi++)
#pragma unroll
            for (int ji = 0; ji < 4; ji++) {
                ar[mi][ji] = 0.f; az[mi][ji] = 0.f;
                ain[mi][ji] = 0.f; ahn[mi][ji] = 0.f;
            }

        // ---- gate GEMM, x part (K = 32): accumulates r, z, i_n ----
#pragma unroll 4
        for (int k = 0; k < II; k++) {
            const float4 a  = *(const float4*)&A[cur][k][tm4];       // warp-uniform broadcast
            const float4 wr = __ldg((const float4*)&g_Wx[k * 384 + j4]);
            const float4 wz = __ldg((const float4*)&g_Wx[k * 384 + 128 + j4]);
            const float4 wn = __ldg((const float4*)&g_Wx[k * 384 + 256 + j4]);
            const float am[4]  = {a.x, a.y, a.z, a.w};
            const float wrv[4] = {wr.x, wr.y, wr.z, wr.w};
            const float wzv[4] = {wz.x, wz.y, wz.z, wz.w};
            const float wnv[4] = {wn.x, wn.y, wn.z, wn.w};
#pragma unroll
            for (int mi = 0; mi < 4; mi++)
#pragma unroll
                for (int ji = 0; ji < 4; ji++) {
                    ar[mi][ji]  = fmaf(am[mi], wrv[ji], ar[mi][ji]);
                    az[mi][ji]  = fmaf(am[mi], wzv[ji], az[mi][ji]);
                    ain[mi][ji] = fmaf(am[mi], wnv[ji], ain[mi][ji]);
                }
        }

        // ---- gate GEMM, h part (K = 128): accumulates r, z, h_n ----
#pragma unroll 4
        for (int k = 0; k < HH; k++) {
            const float4 a  = *(const float4*)&A[cur][32 + k][tm4];
            const float4 wr = __ldg((const float4*)&g_Wh[k * 384 + j4]);
            const float4 wz = __ldg((const float4*)&g_Wh[k * 384 + 128 + j4]);
            const float4 wn = __ldg((const float4*)&g_Wh[k * 384 + 256 + j4]);
            const float am[4]  = {a.x, a.y, a.z, a.w};
            const float wrv[4] = {wr.x, wr.y, wr.z, wr.w};
            const float wzv[4] = {wz.x, wz.y, wz.z, wz.w};
            const float wnv[4] = {wn.x, wn.y, wn.z, wn.w};
#pragma unroll
            for (int mi = 0; mi < 4; mi++)
#pragma unroll
                for (int ji = 0; ji < 4; ji++) {
                    ar[mi][ji]  = fmaf(am[mi], wrv[ji], ar[mi][ji]);
                    az[mi][ji]  = fmaf(am[mi], wzv[ji], az[mi][ji]);
                    ahn[mi][ji] = fmaf(am[mi], wnv[ji], ahn[mi][ji]);
                }
        }

        // ---- activations + h_new -> A[nxt] hidden rows ----
#pragma unroll
        for (int ji = 0; ji < 4; ji++) {
            const float4 hold = *(const float4*)&A[cur][32 + j4 + ji][tm4];
            const float ho[4] = {hold.x, hold.y, hold.z, hold.w};
            float hn[4];
#pragma unroll
            for (int mi = 0; mi < 4; mi++) {
                float r = sigmoid_f(ar[mi][ji] + br_[ji]);
                float z = sigmoid_f(az[mi][ji] + bz_[ji]);
                float n = tanh_f(fmaf(r, ahn[mi][ji] + bhn_[ji],
                                      ain[mi][ji] + bin_[ji]));
                hn[mi] = n + z * (ho[mi] - n);   // (1-z)*n + z*h
            }
            *(float4*)&A[nxt][32 + j4 + ji][tm4] =
                make_float4(hn[0], hn[1], hn[2], hn[3]);
        }
        __syncthreads();   // Hnew complete

        // ---- output GEMM: y = h_new @ W_out^T + b_out (lane = feature i) ----
        float y0 = bo, y1 = bo, y2 = bo, y3 = bo;
#pragma unroll 4
        for (int k = 0; k < HH; k++) {
            const float4 hv = *(const float4*)&A[nxt][32 + k][tm4];  // broadcast
            const float  w  = __ldg(&g_Wot[(k << 5) + tj]);          // coalesced
            y0 = fmaf(hv.x, w, y0);
            y1 = fmaf(hv.y, w, y1);
            y2 = fmaf(hv.z, w, y2);
            y3 = fmaf(hv.w, w, y3);
        }
        const float yv[4] = {y0, y1, y2, y3};
#pragma unroll
        for (int mi = 0; mi < 4; mi++) {
            out[((size_t)(b0 + tm4 + mi) * STEPS + t) * II + tj] = yv[mi];
            A[nxt][tj][tm4 + mi] = yv[mi];   // y feeds back as x_{t+1}
        }
        __syncthreads();   // x part of A[nxt] complete before next step
    }
}

// ---------------------------------------------------------------------------
// Harness entry point
// ---------------------------------------------------------------------------
extern "C" void kernel_launch(void* const* d_in, const int* in_sizes, int n_in,
                              void* d_out, int out_size)
{
    const float* x     = (const float*)d_in[0];
    const float* h     = (const float*)d_in[1];
    const float* W_ih  = (const float*)d_in[2];
    const float* W_hh  = (const float*)d_in[3];
    const float* b_ih  = (const float*)d_in[4];
    const float* b_hh  = (const float*)d_in[5];
    const float* W_out = (const float*)d_in[6];
    const float* b_out = (const float*)d_in[7];
    float* out = (float*)d_out;

    // repack weights (covers 65664 work items)
    pack_kernel<<<257, 256>>>(W_ih, W_hh, W_out, b_ih, b_hh);

    // recurrent kernel: 16384/32 = 512 CTAs
    gru_kernel<<<BB / MT, NTH>>>(x, h, b_out, out);
}